// round 14
// baseline (speedup 1.0000x reference)
#include <cuda_runtime.h>
#include <cuda_bf16.h>
#include <cuda_fp16.h>
#include <cstdint>

// ---------------------------------------------------------------------------
// GQA: B=2, T=2048, C=1024, H=16 q-heads, KVH=4 kv-heads, D=64, causal, RoPE
// Full single-fp16 pipeline (fp32 accum). Q/K head-dims stored PERMUTED in
// interleaved rope-pair order (2j <-> d=j, 2j+1 <-> d=j+32): QK^T invariant,
// RoPE is per-thread register math. Attention: 128-key tiles, cond. rescale.
// ---------------------------------------------------------------------------

__device__ __align__(16) __half g_x[4194304];
__device__ __align__(16) __half g_wqkv[1572864];   // [K=1024][N=1536], Q/K cols permuted
__device__ __align__(16) __half g_wo[1048576];
__device__ __align__(16) __half g_q[4194304];      // permuted head-dim
__device__ __align__(16) __half g_k[1048576];      // permuted head-dim
__device__ __align__(16) __half g_v[1048576];
__device__ __align__(16) __half g_y[4194304];

// ---------------------------------------------------------------------------
// helpers
// ---------------------------------------------------------------------------
__device__ __forceinline__ uint32_t smem_u32(const void* p) {
    return (uint32_t)__cvta_generic_to_shared(p);
}
__device__ __forceinline__ void ldmx4(uint32_t* r, uint32_t addr) {
    asm volatile("ldmatrix.sync.aligned.m8n8.x4.shared.b16 {%0,%1,%2,%3}, [%4];"
        : "=r"(r[0]), "=r"(r[1]), "=r"(r[2]), "=r"(r[3]) : "r"(addr));
}
__device__ __forceinline__ void ldmx4t(uint32_t* r, uint32_t addr) {
    asm volatile("ldmatrix.sync.aligned.m8n8.x4.trans.shared.b16 {%0,%1,%2,%3}, [%4];"
        : "=r"(r[0]), "=r"(r[1]), "=r"(r[2]), "=r"(r[3]) : "r"(addr));
}
__device__ __forceinline__ void mma_f16(float* c, const uint32_t* a, const uint32_t* b) {
    asm volatile(
        "mma.sync.aligned.m16n8k16.row.col.f32.f16.f16.f32 "
        "{%0,%1,%2,%3}, {%4,%5,%6,%7}, {%8,%9}, {%0,%1,%2,%3};\n"
        : "+f"(c[0]), "+f"(c[1]), "+f"(c[2]), "+f"(c[3])
        : "r"(a[0]), "r"(a[1]), "r"(a[2]), "r"(a[3]), "r"(b[0]), "r"(b[1]));
}
__device__ __forceinline__ float ex2(float x) {
    float r;
    asm("ex2.approx.f32 %0, %1;" : "=f"(r) : "f"(x));
    return r;
}
__device__ __forceinline__ void store_h16(__half* H, int idx, float a, float b) {
    __half2 hv = __floats2half2_rn(a, b);
    *(__half2*)(H + idx) = hv;
}
__device__ __forceinline__ uint32_t pack_f16x2(float a, float b) {
    __half2 h = __floats2half2_rn(a, b);
    return *(uint32_t*)&h;
}
__device__ __forceinline__ uint2 cvt4_f16(float4 v) {
    __half2 h0 = __floats2half2_rn(v.x, v.y);
    __half2 h1 = __floats2half2_rn(v.z, v.w);
    uint2 r; r.x = *(uint32_t*)&h0; r.y = *(uint32_t*)&h1;
    return r;
}
__device__ __forceinline__ void cpa16(uint32_t dst, const void* src) {
    asm volatile("cp.async.cg.shared.global [%0], [%1], 16;\n" :: "r"(dst), "l"(src));
}

#define SOFTMAX_SCALE (0.125f * 1.44269504088896f)  // 1/sqrt(64) * log2(e)

// ---------------------------------------------------------------------------
// Single merged conversion kernel (fp32 -> fp16, weights permuted for rope).
// ---------------------------------------------------------------------------
__global__ void cvt_all(const float* __restrict__ x,
                        const float* __restrict__ Wq,
                        const float* __restrict__ Wk,
                        const float* __restrict__ Wv,
                        const float* __restrict__ Wo)
{
    int blk = blockIdx.x;
    if (blk < 4096) {
        int i = blk * 256 + threadIdx.x;
        ((uint2*)g_x)[i] = cvt4_f16(((const float4*)x)[i]);
    } else if (blk < 5632) {
        int i = (blk - 4096) * 256 + threadIdx.x;
        int k  = i / 384;
        int n4 = (i % 384) * 4;
        float4 v;
        if (n4 < 1024) {
            int h = n4 >> 6, ch = n4 & 63, j = ch >> 1;
            const float* wr = Wq + k * 1024 + h * 64;
            v.x = wr[j];      v.y = wr[j + 32];
            v.z = wr[j + 1];  v.w = wr[j + 33];
        } else if (n4 < 1280) {
            int m = n4 - 1024;
            int h = m >> 6, ch = m & 63, j = ch >> 1;
            const float* wr = Wk + k * 256 + h * 64;
            v.x = wr[j];      v.y = wr[j + 32];
            v.z = wr[j + 1];  v.w = wr[j + 33];
        } else {
            v = *(const float4*)(Wv + k * 256 + n4 - 1280);
        }
        *(uint2*)(g_wqkv + k * 1536 + n4) = cvt4_f16(v);
    } else {
        int i = (blk - 5632) * 256 + threadIdx.x;
        ((uint2*)g_wo)[i] = cvt4_f16(((const float4*)Wo)[i]);
    }
}

// ---------------------------------------------------------------------------
// fp16 GEMM (fp32 accum), 3-stage cp.async ring (ONE sync/slab), 2 CTAs/SM.
// MODE 0: tile 128x192, grid 8x32 (single wave); permuted-rope epilogue.
// MODE 1: tile 128x128, grid 8x32; fp32 epilogue -> Cout.
// ---------------------------------------------------------------------------
template<int MODE>
__global__ void __launch_bounds__(256, 2) gemm_fp16(
    const float* __restrict__ cosb,
    const float* __restrict__ sinb,
    float* __restrict__ Cout)
{
    constexpr int NT     = (MODE == 0) ? 192 : 128;
    constexpr int NWARP  = NT / 2;
    constexpr int NF     = NWARP / 8;
    constexpr int BPITCH = NT + 8;
    constexpr int STAGE  = 128 * 40 * 2 + 32 * BPITCH * 2;
    constexpr int BCH    = 32 * (NT / 8);
    constexpr int ITERS  = (512 + BCH) / 256;
    const int ldn = (MODE == 0) ? 1536 : 1024;

    extern __shared__ __align__(16) __half sm[];
    const uint32_t sbase = smem_u32(sm);

    const __half* A = (MODE == 0) ? g_x : g_y;
    const __half* B = (MODE == 0) ? g_wqkv : g_wo;

    const int tid  = threadIdx.x;
    const int lane = tid & 31;
    const int warp = tid >> 5;
    const int wm   = warp >> 1;
    const int wn   = warp & 1;
    const int brow = blockIdx.y * 128;
    const int bcol = blockIdx.x * NT;
    const int t4   = lane & 3;

    float c[2][NF][4];
    #pragma unroll
    for (int mt = 0; mt < 2; mt++)
        #pragma unroll
        for (int nt = 0; nt < NF; nt++)
            #pragma unroll
            for (int i = 0; i < 4; i++) c[mt][nt][i] = 0.f;

    auto stage = [&](int ki, int buf) {
        int kb = ki * 32;
        uint32_t base = sbase + (uint32_t)(buf * STAGE);
        #pragma unroll
        for (int i = 0; i < ITERS; i++) {
            int u = tid + i * 256;
            if (u < 512) {
                int ar = u >> 2, ac8 = (u & 3) << 3;
                cpa16(base + (uint32_t)(ar * 40 + ac8) * 2u,
                      A + (brow + ar) * 1024 + kb + ac8);
            } else {
                int v = u - 512;
                int br2 = v / (NT / 8), bc8 = (v % (NT / 8)) * 8;
                cpa16(base + 10240u + (uint32_t)(br2 * BPITCH + bc8) * 2u,
                      B + (kb + br2) * ldn + bcol + bc8);
            }
        }
        asm volatile("cp.async.commit_group;\n" ::: "memory");
    };

    stage(0, 0);
    stage(1, 1);

    for (int ki = 0; ki < 32; ki++) {
        int buf = ki % 3;
        if (ki == 31) {
            asm volatile("cp.async.wait_group 0;\n" ::: "memory");
        } else {
            asm volatile("cp.async.wait_group 1;\n" ::: "memory");
        }
        __syncthreads();

        uint32_t bA = sbase + (uint32_t)(buf * STAGE);
        uint32_t bB = bA + 10240u;

        #pragma unroll
        for (int ks = 0; ks < 2; ks++) {
            uint32_t a[2][4];
            #pragma unroll
            for (int mt = 0; mt < 2; mt++) {
                uint32_t off = 2u * ((uint32_t)(wm * 32 + mt * 16 + (lane & 15)) * 40
                                     + ks * 16 + ((lane >> 4) << 3));
                ldmx4(a[mt], bA + off);
            }
            #pragma unroll
            for (int npp = 0; npp < NF / 2; npp++) {
                uint32_t b4[4];
                uint32_t off = 2u * ((uint32_t)(ks * 16 + (lane & 15)) * BPITCH
                                     + wn * NWARP + npp * 16 + ((lane >> 4) << 3));
                ldmx4t(b4, bB + off);
                #pragma unroll
                for (int sub = 0; sub < 2; sub++) {
                    mma_f16(c[0][npp * 2 + sub], a[0], &b4[sub * 2]);
                    mma_f16(c[1][npp * 2 + sub], a[1], &b4[sub * 2]);
                }
            }
        }

        if (ki + 2 < 32) stage(ki + 2, (ki + 2) % 3);
    }

    if (MODE == 1) {
        #pragma unroll
        for (int mt = 0; mt < 2; mt++) {
            int r0 = brow + wm * 32 + mt * 16 + (lane >> 2);
            #pragma unroll
            for (int nt = 0; nt < NF; nt++) {
                int cc = bcol + wn * NWARP + nt * 8 + (t4 << 1);
                float2 v0; v0.x = c[mt][nt][0]; v0.y = c[mt][nt][1];
                float2 v1; v1.x = c[mt][nt][2]; v1.y = c[mt][nt][3];
                *(float2*)(Cout + r0 * 1024 + cc)       = v0;
                *(float2*)(Cout + (r0 + 8) * 1024 + cc) = v1;
            }
        }
    } else {
        #pragma unroll
        for (int mt = 0; mt < 2; mt++) {
            int r0 = brow + wm * 32 + mt * 16 + (lane >> 2);
            int r1 = r0 + 8;
            int b0 = r0 >> 11, t0 = r0 & 2047;
            int b1 = r1 >> 11, t1 = r1 & 2047;
            #pragma unroll
            for (int nt = 0; nt < NF; nt++) {
                int cc = bcol + wn * NWARP + nt * 8 + (t4 << 1);
                if (cc < 1280) {
                    bool isq = (cc < 1024);
                    int m  = isq ? cc : cc - 1024;
                    int h  = m >> 6, ch = m & 63, j = ch >> 1;
                    int nh = isq ? 16 : 4;
                    float sc = isq ? SOFTMAX_SCALE : 1.f;
                    __half* H = isq ? g_q : g_k;
                    float cs0 = cosb[t0 * 32 + j], sn0 = sinb[t0 * 32 + j];
                    float cs1 = cosb[t1 * 32 + j], sn1 = sinb[t1 * 32 + j];
                    float x1 = c[mt][nt][0], x2 = c[mt][nt][1];
                    store_h16(H, ((b0 * nh + h) * 2048 + t0) * 64 + ch,
                              (x1 * cs0 - x2 * sn0) * sc, (x2 * cs0 + x1 * sn0) * sc);
                    x1 = c[mt][nt][2]; x2 = c[mt][nt][3];
                    store_h16(H, ((b1 * nh + h) * 2048 + t1) * 64 + ch,
                              (x1 * cs1 - x2 * sn1) * sc, (x2 * cs1 + x1 * sn1) * sc);
                } else {
                    int m = cc - 1280;
                    int h = m >> 6, d = m & 63;
                    store_h16(g_v, ((b0 * 4 + h) * 2048 + t0) * 64 + d,
                              c[mt][nt][0], c[mt][nt][1]);
                    store_h16(g_v, ((b1 * 4 + h) * 2048 + t1) * 64 + d,
                              c[mt][nt][2], c[mt][nt][3]);
                }
            }
        }
    }
}

// ---------------------------------------------------------------------------
// MMA flash attention, fp16 x1, 128-KEY TILES + conditional rescale.
// K/V tiles 128x64 fp16, XOR-swizzled; stage = 32 KB; 2-stage double buffer,
// 3 CTAs/SM (192 KB smem). Block = 128 (4 warps), 64 q rows per CTA.
// grid = (32, 32), heavy CTAs first. ntiles = qt/2 + 1 (trailing half-tile
// keys masked by the per-row causal test; staging stays within T=2048).
// ---------------------------------------------------------------------------
__global__ void __launch_bounds__(128, 3) attn_kernel()
{
    extern __shared__ __align__(16) __half smem[];
    const uint32_t sbase = smem_u32(smem);

    const int tid  = threadIdx.x;
    const int lane = tid & 31;
    const int warp = tid >> 5;
    const int g    = lane >> 2;
    const int t4   = lane & 3;
    const int bh   = blockIdx.y;
    const int b    = bh >> 4, hh = bh & 15;
    const int kh   = hh >> 2;
    const int qt   = (int)gridDim.x - 1 - (int)blockIdx.x;   // heavy first

    const int r0 = qt * 64 + warp * 16 + g;
    const int r1 = r0 + 8;
    const int warp_min_row = qt * 64 + warp * 16;

    uint32_t qf[4][4];
    {
        const __half* q0 = g_q + (bh * 2048 + r0) * 64;
        const __half* q1 = g_q + (bh * 2048 + r1) * 64;
        #pragma unroll
        for (int ks = 0; ks < 4; ks++) {
            int cb = ks * 16 + (t4 << 1);
            qf[ks][0] = *(const uint32_t*)(q0 + cb);
            qf[ks][1] = *(const uint32_t*)(q1 + cb);
            qf[ks][2] = *(const uint32_t*)(q0 + cb + 8);
            qf[ks][3] = *(const uint32_t*)(q1 + cb + 8);
        }
    }

    float o[8][4];
    #pragma unroll
    for (int nt = 0; nt < 8; nt++)
        #pragma unroll
        for (int i = 0; i < 4; i++) o[nt][i] = 0.f;
    float m0 = -1e30f, m1 = -1e30f, l0 = 0.f, l1 = 0.f;

    const __half* srcK = g_k + ((b * 4 + kh) * 2048) * 64;
    const __half* srcV = g_v + ((b * 4 + kh) * 2048) * 64;

    const int ntiles = (qt >> 1) + 1;   // 128-key tiles

    // stage one 128-key K/V tile: 2 arrays x 1024 16B chunks, XOR swizzle
    auto stage = [&](int kt, int buf) {
        uint32_t base = sbase + (uint32_t)buf * 32768u;
        #pragma unroll
        for (int i = 0; i < 8; i++) {
            int u = tid + i * 128;          // 0..1023
            int row = u >> 3, ch = u & 7;
            uint32_t sw = (uint32_t)(row * 128) + (uint32_t)((ch ^ (row & 7)) << 4);
            cpa16(base +           sw, srcK + kt * 8192 + u * 8);
            cpa16(base + 16384u  + sw, srcV + kt * 8192 + u * 8);
        }
        asm volatile("cp.async.commit_group;\n" ::: "memory");
    };

    stage(0, 0);
    if (ntiles > 1) stage(1, 1);

    for (int kt = 0; kt < ntiles; kt++) {
        int buf = kt & 1;
        if (kt == ntiles - 1) {
            asm volatile("cp.async.wait_group 0;\n" ::: "memory");
        } else {
            asm volatile("cp.async.wait_group 1;\n" ::: "memory");
        }
        __syncthreads();

        {
            const uint32_t bK = sbase + (uint32_t)buf * 32768u;
            const uint32_t bV = bK + 16384u;

            float s[16][4];
            #pragma unroll
            for (int nt = 0; nt < 16; nt++)
                #pragma unroll
                for (int i = 0; i < 4; i++) s[nt][i] = 0.f;

            // ---- S = Q K^T over 128 keys ----
            #pragma unroll
            for (int ks = 0; ks < 4; ks++) {
                #pragma unroll
                for (int pr = 0; pr < 8; pr++) {
                    uint32_t kb[4];
                    int n_idx = pr * 16 + (lane & 7) + ((lane >> 4) << 3);
                    int chv   = 2 * ks + ((lane >> 3) & 1);
                    uint32_t off = (uint32_t)(n_idx * 128)
                                 + (uint32_t)((chv ^ (n_idx & 7)) << 4);
                    ldmx4(kb, bK + off);
                    mma_f16(s[pr * 2 + 0], qf[ks], &kb[0]);
                    mma_f16(s[pr * 2 + 1], qf[ks], &kb[2]);
                }
            }

            // ---- causal mask (tiles touching/past the diagonal) ----
            if (kt * 128 + 127 > warp_min_row) {
                #pragma unroll
                for (int nt = 0; nt < 16; nt++) {
                    int c0 = kt * 128 + nt * 8 + (t4 << 1);
                    if (c0     > r0) s[nt][0] = -1e30f;
                    if (c0 + 1 > r0) s[nt][1] = -1e30f;
                    if (c0     > r1) s[nt][2] = -1e30f;
                    if (c0 + 1 > r1) s[nt][3] = -1e30f;
                }
            }

            // ---- online softmax over 128 keys ----
            float t0 = -1e30f, t1 = -1e30f;
            #pragma unroll
            for (int nt = 0; nt < 16; nt++) {
                t0 = fmaxf(t0, fmaxf(s[nt][0], s[nt][1]));
                t1 = fmaxf(t1, fmaxf(s[nt][2], s[nt][3]));
            }
            t0 = fmaxf(t0, __shfl_xor_sync(0xffffffffu, t0, 1));
            t0 = fmaxf(t0, __shfl_xor_sync(0xffffffffu, t0, 2));
            t1 = fmaxf(t1, __shfl_xor_sync(0xffffffffu, t1, 1));
            t1 = fmaxf(t1, __shfl_xor_sync(0xffffffffu, t1, 2));

            if (t0 > m0 || t1 > m1) {            // rescale only when max moves
                float m0n = fmaxf(m0, t0), m1n = fmaxf(m1, t1);
                float c0f = ex2(m0 - m0n), c1f = ex2(m1 - m1n);
                m0 = m0n; m1 = m1n;
                l0 *= c0f; l1 *= c1f;
                #pragma unroll
                for (int nt = 0; nt < 8; nt++) {
                    o[nt][0] *= c0f; o[nt][1] *= c0f;
                    o[nt][2] *= c1f; o[nt][3] *= c1f;
                }
            }

            float sum0 = 0.f, sum1 = 0.f;
            #pragma unroll
            for (int nt = 0; nt < 16; nt++) {
                float p0 = ex2(s[nt][0] - m0);
                float p1 = ex2(s[nt][1] - m0);
                float p2 = ex2(s[nt][2] - m1);
                float p3 = ex2(s[nt][3] - m1);
                sum0 += p0 + p1; sum1 += p2 + p3;
                s[nt][0] = p0; s[nt][1] = p1; s[nt][2] = p2; s[nt][3] = p3;
            }
            l0 += sum0;
            l1 += sum1;

            // ---- O += P V over 128 keys (8 k-steps) ----
            #pragma unroll
            for (int ks = 0; ks < 8; ks++) {
                uint32_t aP[4];
                aP[0] = pack_f16x2(s[2*ks][0],   s[2*ks][1]);
                aP[1] = pack_f16x2(s[2*ks][2],   s[2*ks][3]);
                aP[2] = pack_f16x2(s[2*ks+1][0], s[2*ks+1][1]);
                aP[3] = pack_f16x2(s[2*ks+1][2], s[2*ks+1][3]);

                #pragma unroll
                for (int dp = 0; dp < 4; dp++) {
                    uint32_t vf[4];
                    int row  = 16 * ks + (lane & 15);
                    int chv  = dp * 2 + (lane >> 4);
                    uint32_t off = (uint32_t)(row * 128)
                                 + (uint32_t)((chv ^ (row & 7)) << 4);
                    ldmx4t(vf, bV + off);
                    mma_f16(o[dp * 2 + 0], aP, &vf[0]);
                    mma_f16(o[dp * 2 + 1], aP, &vf[2]);
                }
            }
        }

        // second barrier: all warps done reading this buffer before refill
        __syncthreads();
        if (kt + 2 < ntiles) stage(kt + 2, buf);
    }

    l0 += __shfl_xor_sync(0xffffffffu, l0, 1);
    l0 += __shfl_xor_sync(0xffffffffu, l0, 2);
    l1 += __shfl_xor_sync(0xffffffffu, l1, 1);
    l1 += __shfl_xor_sync(0xffffffffu, l1, 2);
    float inv0 = 1.f / l0, inv1 = 1.f / l1;

    int y0 = (b * 2048 + r0) * 1024 + hh * 64;
    int y1 = (b * 2048 + r1) * 1024 + hh * 64;
    #pragma unroll
    for (int nt = 0; nt < 8; nt++) {
        int d = nt * 8 + (t4 << 1);
        store_h16(g_y, y0 + d, o[nt][0] * inv0, o[nt][1] * inv0);
        store_h16(g_y, y1 + d, o[nt][2] * inv1, o[nt][3] * inv1);
    }
}

// ---------------------------------------------------------------------------
// Launch: x, cos, sin, Wq, Wk, Wv, Wo. out = f32 [B,T,C].
// ---------------------------------------------------------------------------
extern "C" void kernel_launch(void* const* d_in, const int* in_sizes, int n_in,
                              void* d_out, int out_size)
{
    const float* x    = (const float*)d_in[0];
    const float* cosb = (const float*)d_in[1];
    const float* sinb = (const float*)d_in[2];
    const float* Wq   = (const float*)d_in[3];
    const float* Wk   = (const float*)d_in[4];
    const float* Wv   = (const float*)d_in[5];
    const float* Wo   = (const float*)d_in[6];
    float* out = (float*)d_out;

    static bool attr_set = false;
    if (!attr_set) {
        cudaFuncSetAttribute(attn_kernel,
                             cudaFuncAttributeMaxDynamicSharedMemorySize, 65536);
        cudaFuncSetAttribute(gemm_fp16<0>,
                             cudaFuncAttributeMaxDynamicSharedMemorySize, 69120);
        cudaFuncSetAttribute(gemm_fp16<1>,
                             cudaFuncAttributeMaxDynamicSharedMemorySize, 56832);
        attr_set = true;
    }

    // 0. one merged fp32 -> fp16 conversion (weights permuted for rope pairs)
    cvt_all<<<6656, 256>>>(x, Wq, Wk, Wv, Wo);

    // 1. fused QKV projection + RoPE + scale (fp16, tile 128x192, one wave)
    gemm_fp16<0><<<dim3(8, 32), 256, 69120>>>(cosb, sinb, nullptr);

    // 2. causal flash attention (fp16, 128-key tiles, 3 CTAs/SM)
    attn_kernel<<<dim3(32, 32), 128, 65536>>>();

    // 3. output projection (fp16, tile 128x128, single wave)
    gemm_fp16<1><<<dim3(8, 32), 256, 56832>>>(nullptr, nullptr, out);
}

// round 15
// speedup vs baseline: 1.0492x; 1.0492x over previous
#include <cuda_runtime.h>
#include <cuda_bf16.h>
#include <cuda_fp16.h>
#include <cstdint>

// ---------------------------------------------------------------------------
// GQA: B=2, T=2048, C=1024, H=16 q-heads, KVH=4 kv-heads, D=64, causal, RoPE
// Full single-fp16 pipeline (fp32 accum). Q/K head-dims stored PERMUTED in
// interleaved rope-pair order (QK^T invariant; RoPE = register math).
// Attention: 64-key tiles, 3-stage ring, 4 CTAs/SM, TRIANGULAR-PAIRED CTAs
// (each CTA does q-tiles bx and 31-bx -> constant work, single wave).
// ---------------------------------------------------------------------------

__device__ __align__(16) __half g_x[4194304];
__device__ __align__(16) __half g_wqkv[1572864];   // [K=1024][N=1536], Q/K cols permuted
__device__ __align__(16) __half g_wo[1048576];
__device__ __align__(16) __half g_q[4194304];      // permuted head-dim
__device__ __align__(16) __half g_k[1048576];      // permuted head-dim
__device__ __align__(16) __half g_v[1048576];
__device__ __align__(16) __half g_y[4194304];

// ---------------------------------------------------------------------------
// helpers
// ---------------------------------------------------------------------------
__device__ __forceinline__ uint32_t smem_u32(const void* p) {
    return (uint32_t)__cvta_generic_to_shared(p);
}
__device__ __forceinline__ void ldmx4(uint32_t* r, uint32_t addr) {
    asm volatile("ldmatrix.sync.aligned.m8n8.x4.shared.b16 {%0,%1,%2,%3}, [%4];"
        : "=r"(r[0]), "=r"(r[1]), "=r"(r[2]), "=r"(r[3]) : "r"(addr));
}
__device__ __forceinline__ void ldmx4t(uint32_t* r, uint32_t addr) {
    asm volatile("ldmatrix.sync.aligned.m8n8.x4.trans.shared.b16 {%0,%1,%2,%3}, [%4];"
        : "=r"(r[0]), "=r"(r[1]), "=r"(r[2]), "=r"(r[3]) : "r"(addr));
}
__device__ __forceinline__ void mma_f16(float* c, const uint32_t* a, const uint32_t* b) {
    asm volatile(
        "mma.sync.aligned.m16n8k16.row.col.f32.f16.f16.f32 "
        "{%0,%1,%2,%3}, {%4,%5,%6,%7}, {%8,%9}, {%0,%1,%2,%3};\n"
        : "+f"(c[0]), "+f"(c[1]), "+f"(c[2]), "+f"(c[3])
        : "r"(a[0]), "r"(a[1]), "r"(a[2]), "r"(a[3]), "r"(b[0]), "r"(b[1]));
}
__device__ __forceinline__ float ex2(float x) {
    float r;
    asm("ex2.approx.f32 %0, %1;" : "=f"(r) : "f"(x));
    return r;
}
__device__ __forceinline__ void store_h16(__half* H, int idx, float a, float b) {
    __half2 hv = __floats2half2_rn(a, b);
    *(__half2*)(H + idx) = hv;
}
__device__ __forceinline__ uint32_t pack_f16x2(float a, float b) {
    __half2 h = __floats2half2_rn(a, b);
    return *(uint32_t*)&h;
}
__device__ __forceinline__ uint2 cvt4_f16(float4 v) {
    __half2 h0 = __floats2half2_rn(v.x, v.y);
    __half2 h1 = __floats2half2_rn(v.z, v.w);
    uint2 r; r.x = *(uint32_t*)&h0; r.y = *(uint32_t*)&h1;
    return r;
}
__device__ __forceinline__ void cpa16(uint32_t dst, const void* src) {
    asm volatile("cp.async.cg.shared.global [%0], [%1], 16;\n" :: "r"(dst), "l"(src));
}

#define SOFTMAX_SCALE (0.125f * 1.44269504088896f)  // 1/sqrt(64) * log2(e)

// ---------------------------------------------------------------------------
// Single merged conversion kernel (fp32 -> fp16, weights permuted for rope).
// ---------------------------------------------------------------------------
__global__ void cvt_all(const float* __restrict__ x,
                        const float* __restrict__ Wq,
                        const float* __restrict__ Wk,
                        const float* __restrict__ Wv,
                        const float* __restrict__ Wo)
{
    int blk = blockIdx.x;
    if (blk < 4096) {
        int i = blk * 256 + threadIdx.x;
        ((uint2*)g_x)[i] = cvt4_f16(((const float4*)x)[i]);
    } else if (blk < 5632) {
        int i = (blk - 4096) * 256 + threadIdx.x;
        int k  = i / 384;
        int n4 = (i % 384) * 4;
        float4 v;
        if (n4 < 1024) {
            int h = n4 >> 6, ch = n4 & 63, j = ch >> 1;
            const float* wr = Wq + k * 1024 + h * 64;
            v.x = wr[j];      v.y = wr[j + 32];
            v.z = wr[j + 1];  v.w = wr[j + 33];
        } else if (n4 < 1280) {
            int m = n4 - 1024;
            int h = m >> 6, ch = m & 63, j = ch >> 1;
            const float* wr = Wk + k * 256 + h * 64;
            v.x = wr[j];      v.y = wr[j + 32];
            v.z = wr[j + 1];  v.w = wr[j + 33];
        } else {
            v = *(const float4*)(Wv + k * 256 + n4 - 1280);
        }
        *(uint2*)(g_wqkv + k * 1536 + n4) = cvt4_f16(v);
    } else {
        int i = (blk - 5632) * 256 + threadIdx.x;
        ((uint2*)g_wo)[i] = cvt4_f16(((const float4*)Wo)[i]);
    }
}

// ---------------------------------------------------------------------------
// fp16 GEMM (fp32 accum), 3-stage cp.async ring (ONE sync/slab), 2 CTAs/SM.
// MODE 0: tile 128x192, grid 8x32 (single wave); permuted-rope epilogue.
// MODE 1: tile 128x128, grid 8x32; fp32 epilogue -> Cout.
// ---------------------------------------------------------------------------
template<int MODE>
__global__ void __launch_bounds__(256, 2) gemm_fp16(
    const float* __restrict__ cosb,
    const float* __restrict__ sinb,
    float* __restrict__ Cout)
{
    constexpr int NT     = (MODE == 0) ? 192 : 128;
    constexpr int NWARP  = NT / 2;
    constexpr int NF     = NWARP / 8;
    constexpr int BPITCH = NT + 8;
    constexpr int STAGE  = 128 * 40 * 2 + 32 * BPITCH * 2;
    constexpr int BCH    = 32 * (NT / 8);
    constexpr int ITERS  = (512 + BCH) / 256;
    const int ldn = (MODE == 0) ? 1536 : 1024;

    extern __shared__ __align__(16) __half sm[];
    const uint32_t sbase = smem_u32(sm);

    const __half* A = (MODE == 0) ? g_x : g_y;
    const __half* B = (MODE == 0) ? g_wqkv : g_wo;

    const int tid  = threadIdx.x;
    const int lane = tid & 31;
    const int warp = tid >> 5;
    const int wm   = warp >> 1;
    const int wn   = warp & 1;
    const int brow = blockIdx.y * 128;
    const int bcol = blockIdx.x * NT;
    const int t4   = lane & 3;

    float c[2][NF][4];
    #pragma unroll
    for (int mt = 0; mt < 2; mt++)
        #pragma unroll
        for (int nt = 0; nt < NF; nt++)
            #pragma unroll
            for (int i = 0; i < 4; i++) c[mt][nt][i] = 0.f;

    auto stage = [&](int ki, int buf) {
        int kb = ki * 32;
        uint32_t base = sbase + (uint32_t)(buf * STAGE);
        #pragma unroll
        for (int i = 0; i < ITERS; i++) {
            int u = tid + i * 256;
            if (u < 512) {
                int ar = u >> 2, ac8 = (u & 3) << 3;
                cpa16(base + (uint32_t)(ar * 40 + ac8) * 2u,
                      A + (brow + ar) * 1024 + kb + ac8);
            } else {
                int v = u - 512;
                int br2 = v / (NT / 8), bc8 = (v % (NT / 8)) * 8;
                cpa16(base + 10240u + (uint32_t)(br2 * BPITCH + bc8) * 2u,
                      B + (kb + br2) * ldn + bcol + bc8);
            }
        }
        asm volatile("cp.async.commit_group;\n" ::: "memory");
    };

    stage(0, 0);
    stage(1, 1);

    for (int ki = 0; ki < 32; ki++) {
        int buf = ki % 3;
        if (ki == 31) {
            asm volatile("cp.async.wait_group 0;\n" ::: "memory");
        } else {
            asm volatile("cp.async.wait_group 1;\n" ::: "memory");
        }
        __syncthreads();

        uint32_t bA = sbase + (uint32_t)(buf * STAGE);
        uint32_t bB = bA + 10240u;

        #pragma unroll
        for (int ks = 0; ks < 2; ks++) {
            uint32_t a[2][4];
            #pragma unroll
            for (int mt = 0; mt < 2; mt++) {
                uint32_t off = 2u * ((uint32_t)(wm * 32 + mt * 16 + (lane & 15)) * 40
                                     + ks * 16 + ((lane >> 4) << 3));
                ldmx4(a[mt], bA + off);
            }
            #pragma unroll
            for (int npp = 0; npp < NF / 2; npp++) {
                uint32_t b4[4];
                uint32_t off = 2u * ((uint32_t)(ks * 16 + (lane & 15)) * BPITCH
                                     + wn * NWARP + npp * 16 + ((lane >> 4) << 3));
                ldmx4t(b4, bB + off);
                #pragma unroll
                for (int sub = 0; sub < 2; sub++) {
                    mma_f16(c[0][npp * 2 + sub], a[0], &b4[sub * 2]);
                    mma_f16(c[1][npp * 2 + sub], a[1], &b4[sub * 2]);
                }
            }
        }

        if (ki + 2 < 32) stage(ki + 2, (ki + 2) % 3);
    }

    if (MODE == 1) {
        #pragma unroll
        for (int mt = 0; mt < 2; mt++) {
            int r0 = brow + wm * 32 + mt * 16 + (lane >> 2);
            #pragma unroll
            for (int nt = 0; nt < NF; nt++) {
                int cc = bcol + wn * NWARP + nt * 8 + (t4 << 1);
                float2 v0; v0.x = c[mt][nt][0]; v0.y = c[mt][nt][1];
                float2 v1; v1.x = c[mt][nt][2]; v1.y = c[mt][nt][3];
                *(float2*)(Cout + r0 * 1024 + cc)       = v0;
                *(float2*)(Cout + (r0 + 8) * 1024 + cc) = v1;
            }
        }
    } else {
        #pragma unroll
        for (int mt = 0; mt < 2; mt++) {
            int r0 = brow + wm * 32 + mt * 16 + (lane >> 2);
            int r1 = r0 + 8;
            int b0 = r0 >> 11, t0 = r0 & 2047;
            int b1 = r1 >> 11, t1 = r1 & 2047;
            #pragma unroll
            for (int nt = 0; nt < NF; nt++) {
                int cc = bcol + wn * NWARP + nt * 8 + (t4 << 1);
                if (cc < 1280) {
                    bool isq = (cc < 1024);
                    int m  = isq ? cc : cc - 1024;
                    int h  = m >> 6, ch = m & 63, j = ch >> 1;
                    int nh = isq ? 16 : 4;
                    float sc = isq ? SOFTMAX_SCALE : 1.f;
                    __half* H = isq ? g_q : g_k;
                    float cs0 = cosb[t0 * 32 + j], sn0 = sinb[t0 * 32 + j];
                    float cs1 = cosb[t1 * 32 + j], sn1 = sinb[t1 * 32 + j];
                    float x1 = c[mt][nt][0], x2 = c[mt][nt][1];
                    store_h16(H, ((b0 * nh + h) * 2048 + t0) * 64 + ch,
                              (x1 * cs0 - x2 * sn0) * sc, (x2 * cs0 + x1 * sn0) * sc);
                    x1 = c[mt][nt][2]; x2 = c[mt][nt][3];
                    store_h16(H, ((b1 * nh + h) * 2048 + t1) * 64 + ch,
                              (x1 * cs1 - x2 * sn1) * sc, (x2 * cs1 + x1 * sn1) * sc);
                } else {
                    int m = cc - 1280;
                    int h = m >> 6, d = m & 63;
                    store_h16(g_v, ((b0 * 4 + h) * 2048 + t0) * 64 + d,
                              c[mt][nt][0], c[mt][nt][1]);
                    store_h16(g_v, ((b1 * 4 + h) * 2048 + t1) * 64 + d,
                              c[mt][nt][2], c[mt][nt][3]);
                }
            }
        }
    }
}

// ---------------------------------------------------------------------------
// MMA flash attention, fp16 x1, 64-key tiles, 3-stage ring, ONE sync per
// tile, 4 CTAs/SM. TRIANGULAR PAIRING: grid (16, 32); each CTA processes
// q-tiles bx and 31-bx sequentially -> constant 33 tiles per CTA, one wave.
// Conditional rescale: o/l rescale only when the running max moves.
// ---------------------------------------------------------------------------
__global__ void __launch_bounds__(128, 4) attn_kernel()
{
    extern __shared__ __align__(16) __half smem[];
    const uint32_t sbase = smem_u32(smem);

    const int tid  = threadIdx.x;
    const int lane = tid & 31;
    const int warp = tid >> 5;
    const int g    = lane >> 2;
    const int t4   = lane & 3;
    const int bh   = blockIdx.y;
    const int b    = bh >> 4, hh = bh & 15;
    const int kh   = hh >> 2;

    const __half* srcK = g_k + ((b * 4 + kh) * 2048) * 64;
    const __half* srcV = g_v + ((b * 4 + kh) * 2048) * 64;

    auto stage = [&](int kt, int buf) {
        uint32_t base = sbase + (uint32_t)buf * 16384u;
        #pragma unroll
        for (int i = 0; i < 4; i++) {
            int u = tid + i * 128;
            int row = u >> 3, ch = u & 7;
            uint32_t sw = (uint32_t)(row * 128) + (uint32_t)((ch ^ (row & 7)) << 4);
            cpa16(base +          sw, srcK + kt * 4096 + u * 8);
            cpa16(base + 8192u  + sw, srcV + kt * 4096 + u * 8);
        }
        asm volatile("cp.async.commit_group;\n" ::: "memory");
    };

    #pragma unroll 1
    for (int ph = 0; ph < 2; ph++) {
        const int qt = ph ? (31 - (int)blockIdx.x) : (int)blockIdx.x;

        const int r0 = qt * 64 + warp * 16 + g;
        const int r1 = r0 + 8;
        const int warp_min_row = qt * 64 + warp * 16;

        uint32_t qf[4][4];
        {
            const __half* q0 = g_q + (bh * 2048 + r0) * 64;
            const __half* q1 = g_q + (bh * 2048 + r1) * 64;
            #pragma unroll
            for (int ks = 0; ks < 4; ks++) {
                int cb = ks * 16 + (t4 << 1);
                qf[ks][0] = *(const uint32_t*)(q0 + cb);
                qf[ks][1] = *(const uint32_t*)(q1 + cb);
                qf[ks][2] = *(const uint32_t*)(q0 + cb + 8);
                qf[ks][3] = *(const uint32_t*)(q1 + cb + 8);
            }
        }

        float o[8][4];
        #pragma unroll
        for (int nt = 0; nt < 8; nt++)
            #pragma unroll
            for (int i = 0; i < 4; i++) o[nt][i] = 0.f;
        float m0 = -1e30f, m1 = -1e30f, l0 = 0.f, l1 = 0.f;

        const int ntiles = qt + 1;

        stage(0, 0);
        if (ntiles > 1) stage(1, 1);

        for (int kt = 0; kt < ntiles; kt++) {
            int buf = kt % 3;
            if (kt == ntiles - 1) {
                asm volatile("cp.async.wait_group 0;\n" ::: "memory");
            } else {
                asm volatile("cp.async.wait_group 1;\n" ::: "memory");
            }
            __syncthreads();

            {
                const uint32_t bK = sbase + (uint32_t)buf * 16384u;
                const uint32_t bV = bK + 8192u;

                float s[8][4];
                #pragma unroll
                for (int nt = 0; nt < 8; nt++)
                    #pragma unroll
                    for (int i = 0; i < 4; i++) s[nt][i] = 0.f;

                #pragma unroll
                for (int ks = 0; ks < 4; ks++) {
                    uint32_t kb[4][4];
                    #pragma unroll
                    for (int pr = 0; pr < 4; pr++) {
                        int n_idx = pr * 16 + (lane & 7) + ((lane >> 4) << 3);
                        int chv   = 2 * ks + ((lane >> 3) & 1);
                        uint32_t off = (uint32_t)(n_idx * 128)
                                     + (uint32_t)((chv ^ (n_idx & 7)) << 4);
                        ldmx4(kb[pr], bK + off);
                    }
                    #pragma unroll
                    for (int pr = 0; pr < 4; pr++)
                        #pragma unroll
                        for (int sub = 0; sub < 2; sub++)
                            mma_f16(s[pr * 2 + sub], qf[ks], &kb[pr][sub * 2]);
                }

                if (kt * 64 + 63 > warp_min_row) {
                    #pragma unroll
                    for (int nt = 0; nt < 8; nt++) {
                        int c0 = kt * 64 + nt * 8 + (t4 << 1);
                        if (c0     > r0) s[nt][0] = -1e30f;
                        if (c0 + 1 > r0) s[nt][1] = -1e30f;
                        if (c0     > r1) s[nt][2] = -1e30f;
                        if (c0 + 1 > r1) s[nt][3] = -1e30f;
                    }
                }

                float t0 = -1e30f, t1 = -1e30f;
                #pragma unroll
                for (int nt = 0; nt < 8; nt++) {
                    t0 = fmaxf(t0, fmaxf(s[nt][0], s[nt][1]));
                    t1 = fmaxf(t1, fmaxf(s[nt][2], s[nt][3]));
                }
                t0 = fmaxf(t0, __shfl_xor_sync(0xffffffffu, t0, 1));
                t0 = fmaxf(t0, __shfl_xor_sync(0xffffffffu, t0, 2));
                t1 = fmaxf(t1, __shfl_xor_sync(0xffffffffu, t1, 1));
                t1 = fmaxf(t1, __shfl_xor_sync(0xffffffffu, t1, 2));

                if (t0 > m0 || t1 > m1) {        // rescale only when max moves
                    float m0n = fmaxf(m0, t0), m1n = fmaxf(m1, t1);
                    float c0f = ex2(m0 - m0n), c1f = ex2(m1 - m1n);
                    m0 = m0n; m1 = m1n;
                    l0 *= c0f; l1 *= c1f;
                    #pragma unroll
                    for (int nt = 0; nt < 8; nt++) {
                        o[nt][0] *= c0f; o[nt][1] *= c0f;
                        o[nt][2] *= c1f; o[nt][3] *= c1f;
                    }
                }

                float sum0 = 0.f, sum1 = 0.f;
                #pragma unroll
                for (int nt = 0; nt < 8; nt++) {
                    float p0 = ex2(s[nt][0] - m0);
                    float p1 = ex2(s[nt][1] - m0);
                    float p2 = ex2(s[nt][2] - m1);
                    float p3 = ex2(s[nt][3] - m1);
                    sum0 += p0 + p1; sum1 += p2 + p3;
                    s[nt][0] = p0; s[nt][1] = p1; s[nt][2] = p2; s[nt][3] = p3;
                }
                l0 += sum0;
                l1 += sum1;

                #pragma unroll
                for (int ks = 0; ks < 4; ks++) {
                    uint32_t aP[4];
                    aP[0] = pack_f16x2(s[2*ks][0],   s[2*ks][1]);
                    aP[1] = pack_f16x2(s[2*ks][2],   s[2*ks][3]);
                    aP[2] = pack_f16x2(s[2*ks+1][0], s[2*ks+1][1]);
                    aP[3] = pack_f16x2(s[2*ks+1][2], s[2*ks+1][3]);

                    #pragma unroll
                    for (int dp = 0; dp < 4; dp++) {
                        uint32_t vf[4];
                        int row  = 16 * ks + (lane & 15);
                        int chv  = dp * 2 + (lane >> 4);
                        uint32_t off = (uint32_t)(row * 128)
                                     + (uint32_t)((chv ^ (row & 7)) << 4);
                        ldmx4t(vf, bV + off);
                        mma_f16(o[dp * 2 + 0], aP, &vf[0]);
                        mma_f16(o[dp * 2 + 1], aP, &vf[2]);
                    }
                }
            }

            if (kt + 2 < ntiles) stage(kt + 2, (kt + 2) % 3);
        }

        l0 += __shfl_xor_sync(0xffffffffu, l0, 1);
        l0 += __shfl_xor_sync(0xffffffffu, l0, 2);
        l1 += __shfl_xor_sync(0xffffffffu, l1, 1);
        l1 += __shfl_xor_sync(0xffffffffu, l1, 2);
        float inv0 = 1.f / l0, inv1 = 1.f / l1;

        int y0 = (b * 2048 + r0) * 1024 + hh * 64;
        int y1 = (b * 2048 + r1) * 1024 + hh * 64;
        #pragma unroll
        for (int nt = 0; nt < 8; nt++) {
            int d = nt * 8 + (t4 << 1);
            store_h16(g_y, y0 + d, o[nt][0] * inv0, o[nt][1] * inv0);
            store_h16(g_y, y1 + d, o[nt][2] * inv1, o[nt][3] * inv1);
        }

        // ensure all warps finished reading smem before next phase restages
        __syncthreads();
    }
}

// ---------------------------------------------------------------------------
// Launch: x, cos, sin, Wq, Wk, Wv, Wo. out = f32 [B,T,C].
// ---------------------------------------------------------------------------
extern "C" void kernel_launch(void* const* d_in, const int* in_sizes, int n_in,
                              void* d_out, int out_size)
{
    const float* x    = (const float*)d_in[0];
    const float* cosb = (const float*)d_in[1];
    const float* sinb = (const float*)d_in[2];
    const float* Wq   = (const float*)d_in[3];
    const float* Wk   = (const float*)d_in[4];
    const float* Wv   = (const float*)d_in[5];
    const float* Wo   = (const float*)d_in[6];
    float* out = (float*)d_out;

    static bool attr_set = false;
    if (!attr_set) {
        cudaFuncSetAttribute(attn_kernel,
                             cudaFuncAttributeMaxDynamicSharedMemorySize, 49152);
        cudaFuncSetAttribute(gemm_fp16<0>,
                             cudaFuncAttributeMaxDynamicSharedMemorySize, 69120);
        cudaFuncSetAttribute(gemm_fp16<1>,
                             cudaFuncAttributeMaxDynamicSharedMemorySize, 56832);
        attr_set = true;
    }

    // 0. one merged fp32 -> fp16 conversion (weights permuted for rope pairs)
    cvt_all<<<6656, 256>>>(x, Wq, Wk, Wv, Wo);

    // 1. fused QKV projection + RoPE + scale (fp16, tile 128x192, one wave)
    gemm_fp16<0><<<dim3(8, 32), 256, 69120>>>(cosb, sinb, nullptr);

    // 2. causal flash attention (fp16, paired q-tiles, single balanced wave)
    attn_kernel<<<dim3(16, 32), 128, 49152>>>();

    // 3. output projection (fp16, tile 128x128, single wave)
    gemm_fp16<1><<<dim3(8, 32), 256, 56832>>>(nullptr, nullptr, out);
}

// round 16
// speedup vs baseline: 1.0631x; 1.0133x over previous
#include <cuda_runtime.h>
#include <cuda_bf16.h>
#include <cuda_fp16.h>
#include <cstdint>

// ---------------------------------------------------------------------------
// GQA: B=2, T=2048, C=1024, H=16 q-heads, KVH=4 kv-heads, D=64, causal, RoPE
// Full single-fp16 pipeline (fp32 accum). Q/K head-dims stored PERMUTED in
// interleaved rope-pair order (QK^T invariant; RoPE = register math).
// GEMMs: BK=64 slabs (half the barriers). Attention: 64-key tiles, 3-stage
// ring, 4 CTAs/SM, triangular-paired CTAs, conditional rescale.
// ---------------------------------------------------------------------------

__device__ __align__(16) __half g_x[4194304];
__device__ __align__(16) __half g_wqkv[1572864];   // [K=1024][N=1536], Q/K cols permuted
__device__ __align__(16) __half g_wo[1048576];
__device__ __align__(16) __half g_q[4194304];      // permuted head-dim
__device__ __align__(16) __half g_k[1048576];      // permuted head-dim
__device__ __align__(16) __half g_v[1048576];
__device__ __align__(16) __half g_y[4194304];

// ---------------------------------------------------------------------------
// helpers
// ---------------------------------------------------------------------------
__device__ __forceinline__ uint32_t smem_u32(const void* p) {
    return (uint32_t)__cvta_generic_to_shared(p);
}
__device__ __forceinline__ void ldmx4(uint32_t* r, uint32_t addr) {
    asm volatile("ldmatrix.sync.aligned.m8n8.x4.shared.b16 {%0,%1,%2,%3}, [%4];"
        : "=r"(r[0]), "=r"(r[1]), "=r"(r[2]), "=r"(r[3]) : "r"(addr));
}
__device__ __forceinline__ void ldmx4t(uint32_t* r, uint32_t addr) {
    asm volatile("ldmatrix.sync.aligned.m8n8.x4.trans.shared.b16 {%0,%1,%2,%3}, [%4];"
        : "=r"(r[0]), "=r"(r[1]), "=r"(r[2]), "=r"(r[3]) : "r"(addr));
}
__device__ __forceinline__ void mma_f16(float* c, const uint32_t* a, const uint32_t* b) {
    asm volatile(
        "mma.sync.aligned.m16n8k16.row.col.f32.f16.f16.f32 "
        "{%0,%1,%2,%3}, {%4,%5,%6,%7}, {%8,%9}, {%0,%1,%2,%3};\n"
        : "+f"(c[0]), "+f"(c[1]), "+f"(c[2]), "+f"(c[3])
        : "r"(a[0]), "r"(a[1]), "r"(a[2]), "r"(a[3]), "r"(b[0]), "r"(b[1]));
}
__device__ __forceinline__ float ex2(float x) {
    float r;
    asm("ex2.approx.f32 %0, %1;" : "=f"(r) : "f"(x));
    return r;
}
__device__ __forceinline__ void store_h16(__half* H, int idx, float a, float b) {
    __half2 hv = __floats2half2_rn(a, b);
    *(__half2*)(H + idx) = hv;
}
__device__ __forceinline__ uint32_t pack_f16x2(float a, float b) {
    __half2 h = __floats2half2_rn(a, b);
    return *(uint32_t*)&h;
}
__device__ __forceinline__ uint2 cvt4_f16(float4 v) {
    __half2 h0 = __floats2half2_rn(v.x, v.y);
    __half2 h1 = __floats2half2_rn(v.z, v.w);
    uint2 r; r.x = *(uint32_t*)&h0; r.y = *(uint32_t*)&h1;
    return r;
}
__device__ __forceinline__ void cpa16(uint32_t dst, const void* src) {
    asm volatile("cp.async.cg.shared.global [%0], [%1], 16;\n" :: "r"(dst), "l"(src));
}

#define SOFTMAX_SCALE (0.125f * 1.44269504088896f)  // 1/sqrt(64) * log2(e)

// ---------------------------------------------------------------------------
// Single merged conversion kernel (fp32 -> fp16, weights permuted for rope).
// ---------------------------------------------------------------------------
__global__ void cvt_all(const float* __restrict__ x,
                        const float* __restrict__ Wq,
                        const float* __restrict__ Wk,
                        const float* __restrict__ Wv,
                        const float* __restrict__ Wo)
{
    int blk = blockIdx.x;
    if (blk < 4096) {
        int i = blk * 256 + threadIdx.x;
        ((uint2*)g_x)[i] = cvt4_f16(((const float4*)x)[i]);
    } else if (blk < 5632) {
        int i = (blk - 4096) * 256 + threadIdx.x;
        int k  = i / 384;
        int n4 = (i % 384) * 4;
        float4 v;
        if (n4 < 1024) {
            int h = n4 >> 6, ch = n4 & 63, j = ch >> 1;
            const float* wr = Wq + k * 1024 + h * 64;
            v.x = wr[j];      v.y = wr[j + 32];
            v.z = wr[j + 1];  v.w = wr[j + 33];
        } else if (n4 < 1280) {
            int m = n4 - 1024;
            int h = m >> 6, ch = m & 63, j = ch >> 1;
            const float* wr = Wk + k * 256 + h * 64;
            v.x = wr[j];      v.y = wr[j + 32];
            v.z = wr[j + 1];  v.w = wr[j + 33];
        } else {
            v = *(const float4*)(Wv + k * 256 + n4 - 1280);
        }
        *(uint2*)(g_wqkv + k * 1536 + n4) = cvt4_f16(v);
    } else {
        int i = (blk - 5632) * 256 + threadIdx.x;
        ((uint2*)g_wo)[i] = cvt4_f16(((const float4*)Wo)[i]);
    }
}

// ---------------------------------------------------------------------------
// fp16 GEMM (fp32 accum), BK=64 slabs (16 barriers total), 2 CTAs/SM.
// MODE 0: tile 128x192, grid 8x32 (single wave), 2-stage buffer;
//         permuted-rope epilogue -> g_q/g_k/g_v.
// MODE 1: tile 128x128, grid 8x32, 3-stage ring; fp32 epilogue -> Cout.
// A tile 128x64 (pitch 72 halves); B tile 64xNT (pitch NT+8).
// ---------------------------------------------------------------------------
template<int MODE>
__global__ void __launch_bounds__(256, 2) gemm_fp16(
    const float* __restrict__ cosb,
    const float* __restrict__ sinb,
    float* __restrict__ Cout)
{
    constexpr int NT     = (MODE == 0) ? 192 : 128;
    constexpr int NWARP  = NT / 2;
    constexpr int NF     = NWARP / 8;
    constexpr int BPITCH = NT + 8;
    constexpr int ABYTES = 128 * 72 * 2;              // 18432
    constexpr int BBYTES = 64 * BPITCH * 2;
    constexpr int STAGE  = ABYTES + BBYTES;
    constexpr int NSTAGE = (MODE == 0) ? 2 : 3;
    constexpr int BCH    = 64 * (NT / 8);             // B 16B-chunks per stage
    constexpr int ITERS  = (1024 + BCH) / 256;
    const int ldn = (MODE == 0) ? 1536 : 1024;

    extern __shared__ __align__(16) __half sm[];
    const uint32_t sbase = smem_u32(sm);

    const __half* A = (MODE == 0) ? g_x : g_y;
    const __half* B = (MODE == 0) ? g_wqkv : g_wo;

    const int tid  = threadIdx.x;
    const int lane = tid & 31;
    const int warp = tid >> 5;
    const int wm   = warp >> 1;
    const int wn   = warp & 1;
    const int brow = blockIdx.y * 128;
    const int bcol = blockIdx.x * NT;
    const int t4   = lane & 3;

    float c[2][NF][4];
    #pragma unroll
    for (int mt = 0; mt < 2; mt++)
        #pragma unroll
        for (int nt = 0; nt < NF; nt++)
            #pragma unroll
            for (int i = 0; i < 4; i++) c[mt][nt][i] = 0.f;

    auto stage = [&](int ki, int buf) {
        int kb = ki * 64;
        uint32_t base = sbase + (uint32_t)(buf * STAGE);
        #pragma unroll
        for (int i = 0; i < ITERS; i++) {
            int u = tid + i * 256;
            if (u < 1024) {
                int ar = u >> 3, ac8 = (u & 7) << 3;
                cpa16(base + (uint32_t)(ar * 72 + ac8) * 2u,
                      A + (brow + ar) * 1024 + kb + ac8);
            } else {
                int v = u - 1024;
                int br2 = v / (NT / 8), bc8 = (v % (NT / 8)) * 8;
                cpa16(base + (uint32_t)ABYTES + (uint32_t)(br2 * BPITCH + bc8) * 2u,
                      B + (kb + br2) * ldn + bcol + bc8);
            }
        }
        asm volatile("cp.async.commit_group;\n" ::: "memory");
    };

    stage(0, 0);
    if (NSTAGE == 3) stage(1, 1);

    for (int ki = 0; ki < 16; ki++) {
        int buf = ki % NSTAGE;
        if (NSTAGE == 3) {
            if (ki == 15) asm volatile("cp.async.wait_group 0;\n" ::: "memory");
            else          asm volatile("cp.async.wait_group 1;\n" ::: "memory");
        } else {
            asm volatile("cp.async.wait_group 0;\n" ::: "memory");
        }
        __syncthreads();

        // prefetch: safe after barrier (target slot freed by previous iter)
        if (NSTAGE == 3) {
            if (ki + 2 < 16) stage(ki + 2, (ki + 2) % 3);
        } else {
            if (ki + 1 < 16) stage(ki + 1, (ki + 1) & 1);
        }

        uint32_t bA = sbase + (uint32_t)(buf * STAGE);
        uint32_t bB = bA + (uint32_t)ABYTES;

        #pragma unroll
        for (int ks = 0; ks < 4; ks++) {
            uint32_t a[2][4];
            #pragma unroll
            for (int mt = 0; mt < 2; mt++) {
                uint32_t off = 2u * ((uint32_t)(wm * 32 + mt * 16 + (lane & 15)) * 72
                                     + ks * 16 + ((lane >> 4) << 3));
                ldmx4(a[mt], bA + off);
            }
            #pragma unroll
            for (int npp = 0; npp < NF / 2; npp++) {
                uint32_t b4[4];
                uint32_t off = 2u * ((uint32_t)(ks * 16 + (lane & 15)) * BPITCH
                                     + wn * NWARP + npp * 16 + ((lane >> 4) << 3));
                ldmx4t(b4, bB + off);
                #pragma unroll
                for (int sub = 0; sub < 2; sub++) {
                    mma_f16(c[0][npp * 2 + sub], a[0], &b4[sub * 2]);
                    mma_f16(c[1][npp * 2 + sub], a[1], &b4[sub * 2]);
                }
            }
        }
    }

    if (MODE == 1) {
        #pragma unroll
        for (int mt = 0; mt < 2; mt++) {
            int r0 = brow + wm * 32 + mt * 16 + (lane >> 2);
            #pragma unroll
            for (int nt = 0; nt < NF; nt++) {
                int cc = bcol + wn * NWARP + nt * 8 + (t4 << 1);
                float2 v0; v0.x = c[mt][nt][0]; v0.y = c[mt][nt][1];
                float2 v1; v1.x = c[mt][nt][2]; v1.y = c[mt][nt][3];
                *(float2*)(Cout + r0 * 1024 + cc)       = v0;
                *(float2*)(Cout + (r0 + 8) * 1024 + cc) = v1;
            }
        }
    } else {
        #pragma unroll
        for (int mt = 0; mt < 2; mt++) {
            int r0 = brow + wm * 32 + mt * 16 + (lane >> 2);
            int r1 = r0 + 8;
            int b0 = r0 >> 11, t0 = r0 & 2047;
            int b1 = r1 >> 11, t1 = r1 & 2047;
            #pragma unroll
            for (int nt = 0; nt < NF; nt++) {
                int cc = bcol + wn * NWARP + nt * 8 + (t4 << 1);
                if (cc < 1280) {
                    bool isq = (cc < 1024);
                    int m  = isq ? cc : cc - 1024;
                    int h  = m >> 6, ch = m & 63, j = ch >> 1;
                    int nh = isq ? 16 : 4;
                    float sc = isq ? SOFTMAX_SCALE : 1.f;
                    __half* H = isq ? g_q : g_k;
                    float cs0 = cosb[t0 * 32 + j], sn0 = sinb[t0 * 32 + j];
                    float cs1 = cosb[t1 * 32 + j], sn1 = sinb[t1 * 32 + j];
                    float x1 = c[mt][nt][0], x2 = c[mt][nt][1];
                    store_h16(H, ((b0 * nh + h) * 2048 + t0) * 64 + ch,
                              (x1 * cs0 - x2 * sn0) * sc, (x2 * cs0 + x1 * sn0) * sc);
                    x1 = c[mt][nt][2]; x2 = c[mt][nt][3];
                    store_h16(H, ((b1 * nh + h) * 2048 + t1) * 64 + ch,
                              (x1 * cs1 - x2 * sn1) * sc, (x2 * cs1 + x1 * sn1) * sc);
                } else {
                    int m = cc - 1280;
                    int h = m >> 6, d = m & 63;
                    store_h16(g_v, ((b0 * 4 + h) * 2048 + t0) * 64 + d,
                              c[mt][nt][0], c[mt][nt][1]);
                    store_h16(g_v, ((b1 * 4 + h) * 2048 + t1) * 64 + d,
                              c[mt][nt][2], c[mt][nt][3]);
                }
            }
        }
    }
}

// ---------------------------------------------------------------------------
// MMA flash attention, fp16 x1, 64-key tiles, 3-stage ring, ONE sync per
// tile, 4 CTAs/SM. TRIANGULAR PAIRING: grid (16, 32); each CTA processes
// q-tiles bx and 31-bx sequentially -> constant 33 tiles per CTA, one wave.
// Conditional rescale: o/l rescale only when the running max moves.
// ---------------------------------------------------------------------------
__global__ void __launch_bounds__(128, 4) attn_kernel()
{
    extern __shared__ __align__(16) __half smem[];
    const uint32_t sbase = smem_u32(smem);

    const int tid  = threadIdx.x;
    const int lane = tid & 31;
    const int warp = tid >> 5;
    const int g    = lane >> 2;
    const int t4   = lane & 3;
    const int bh   = blockIdx.y;
    const int b    = bh >> 4, hh = bh & 15;
    const int kh   = hh >> 2;

    const __half* srcK = g_k + ((b * 4 + kh) * 2048) * 64;
    const __half* srcV = g_v + ((b * 4 + kh) * 2048) * 64;

    auto stage = [&](int kt, int buf) {
        uint32_t base = sbase + (uint32_t)buf * 16384u;
        #pragma unroll
        for (int i = 0; i < 4; i++) {
            int u = tid + i * 128;
            int row = u >> 3, ch = u & 7;
            uint32_t sw = (uint32_t)(row * 128) + (uint32_t)((ch ^ (row & 7)) << 4);
            cpa16(base +          sw, srcK + kt * 4096 + u * 8);
            cpa16(base + 8192u  + sw, srcV + kt * 4096 + u * 8);
        }
        asm volatile("cp.async.commit_group;\n" ::: "memory");
    };

    #pragma unroll 1
    for (int ph = 0; ph < 2; ph++) {
        const int qt = ph ? (31 - (int)blockIdx.x) : (int)blockIdx.x;

        const int r0 = qt * 64 + warp * 16 + g;
        const int r1 = r0 + 8;
        const int warp_min_row = qt * 64 + warp * 16;

        uint32_t qf[4][4];
        {
            const __half* q0 = g_q + (bh * 2048 + r0) * 64;
            const __half* q1 = g_q + (bh * 2048 + r1) * 64;
            #pragma unroll
            for (int ks = 0; ks < 4; ks++) {
                int cb = ks * 16 + (t4 << 1);
                qf[ks][0] = *(const uint32_t*)(q0 + cb);
                qf[ks][1] = *(const uint32_t*)(q1 + cb);
                qf[ks][2] = *(const uint32_t*)(q0 + cb + 8);
                qf[ks][3] = *(const uint32_t*)(q1 + cb + 8);
            }
        }

        float o[8][4];
        #pragma unroll
        for (int nt = 0; nt < 8; nt++)
            #pragma unroll
            for (int i = 0; i < 4; i++) o[nt][i] = 0.f;
        float m0 = -1e30f, m1 = -1e30f, l0 = 0.f, l1 = 0.f;

        const int ntiles = qt + 1;

        stage(0, 0);
        if (ntiles > 1) stage(1, 1);

        for (int kt = 0; kt < ntiles; kt++) {
            int buf = kt % 3;
            if (kt == ntiles - 1) {
                asm volatile("cp.async.wait_group 0;\n" ::: "memory");
            } else {
                asm volatile("cp.async.wait_group 1;\n" ::: "memory");
            }
            __syncthreads();

            {
                const uint32_t bK = sbase + (uint32_t)buf * 16384u;
                const uint32_t bV = bK + 8192u;

                float s[8][4];
                #pragma unroll
                for (int nt = 0; nt < 8; nt++)
                    #pragma unroll
                    for (int i = 0; i < 4; i++) s[nt][i] = 0.f;

                #pragma unroll
                for (int ks = 0; ks < 4; ks++) {
                    uint32_t kb[4][4];
                    #pragma unroll
                    for (int pr = 0; pr < 4; pr++) {
                        int n_idx = pr * 16 + (lane & 7) + ((lane >> 4) << 3);
                        int chv   = 2 * ks + ((lane >> 3) & 1);
                        uint32_t off = (uint32_t)(n_idx * 128)
                                     + (uint32_t)((chv ^ (n_idx & 7)) << 4);
                        ldmx4(kb[pr], bK + off);
                    }
                    #pragma unroll
                    for (int pr = 0; pr < 4; pr++)
                        #pragma unroll
                        for (int sub = 0; sub < 2; sub++)
                            mma_f16(s[pr * 2 + sub], qf[ks], &kb[pr][sub * 2]);
                }

                if (kt * 64 + 63 > warp_min_row) {
                    #pragma unroll
                    for (int nt = 0; nt < 8; nt++) {
                        int c0 = kt * 64 + nt * 8 + (t4 << 1);
                        if (c0     > r0) s[nt][0] = -1e30f;
                        if (c0 + 1 > r0) s[nt][1] = -1e30f;
                        if (c0     > r1) s[nt][2] = -1e30f;
                        if (c0 + 1 > r1) s[nt][3] = -1e30f;
                    }
                }

                float t0 = -1e30f, t1 = -1e30f;
                #pragma unroll
                for (int nt = 0; nt < 8; nt++) {
                    t0 = fmaxf(t0, fmaxf(s[nt][0], s[nt][1]));
                    t1 = fmaxf(t1, fmaxf(s[nt][2], s[nt][3]));
                }
                t0 = fmaxf(t0, __shfl_xor_sync(0xffffffffu, t0, 1));
                t0 = fmaxf(t0, __shfl_xor_sync(0xffffffffu, t0, 2));
                t1 = fmaxf(t1, __shfl_xor_sync(0xffffffffu, t1, 1));
                t1 = fmaxf(t1, __shfl_xor_sync(0xffffffffu, t1, 2));

                if (t0 > m0 || t1 > m1) {
                    float m0n = fmaxf(m0, t0), m1n = fmaxf(m1, t1);
                    float c0f = ex2(m0 - m0n), c1f = ex2(m1 - m1n);
                    m0 = m0n; m1 = m1n;
                    l0 *= c0f; l1 *= c1f;
                    #pragma unroll
                    for (int nt = 0; nt < 8; nt++) {
                        o[nt][0] *= c0f; o[nt][1] *= c0f;
                        o[nt][2] *= c1f; o[nt][3] *= c1f;
                    }
                }

                float sum0 = 0.f, sum1 = 0.f;
                #pragma unroll
                for (int nt = 0; nt < 8; nt++) {
                    float p0 = ex2(s[nt][0] - m0);
                    float p1 = ex2(s[nt][1] - m0);
                    float p2 = ex2(s[nt][2] - m1);
                    float p3 = ex2(s[nt][3] - m1);
                    sum0 += p0 + p1; sum1 += p2 + p3;
                    s[nt][0] = p0; s[nt][1] = p1; s[nt][2] = p2; s[nt][3] = p3;
                }
                l0 += sum0;
                l1 += sum1;

                #pragma unroll
                for (int ks = 0; ks < 4; ks++) {
                    uint32_t aP[4];
                    aP[0] = pack_f16x2(s[2*ks][0],   s[2*ks][1]);
                    aP[1] = pack_f16x2(s[2*ks][2],   s[2*ks][3]);
                    aP[2] = pack_f16x2(s[2*ks+1][0], s[2*ks+1][1]);
                    aP[3] = pack_f16x2(s[2*ks+1][2], s[2*ks+1][3]);

                    #pragma unroll
                    for (int dp = 0; dp < 4; dp++) {
                        uint32_t vf[4];
                        int row  = 16 * ks + (lane & 15);
                        int chv  = dp * 2 + (lane >> 4);
                        uint32_t off = (uint32_t)(row * 128)
                                     + (uint32_t)((chv ^ (row & 7)) << 4);
                        ldmx4t(vf, bV + off);
                        mma_f16(o[dp * 2 + 0], aP, &vf[0]);
                        mma_f16(o[dp * 2 + 1], aP, &vf[2]);
                    }
                }
            }

            if (kt + 2 < ntiles) stage(kt + 2, (kt + 2) % 3);
        }

        l0 += __shfl_xor_sync(0xffffffffu, l0, 1);
        l0 += __shfl_xor_sync(0xffffffffu, l0, 2);
        l1 += __shfl_xor_sync(0xffffffffu, l1, 1);
        l1 += __shfl_xor_sync(0xffffffffu, l1, 2);
        float inv0 = 1.f / l0, inv1 = 1.f / l1;

        int y0 = (b * 2048 + r0) * 1024 + hh * 64;
        int y1 = (b * 2048 + r1) * 1024 + hh * 64;
        #pragma unroll
        for (int nt = 0; nt < 8; nt++) {
            int d = nt * 8 + (t4 << 1);
            store_h16(g_y, y0 + d, o[nt][0] * inv0, o[nt][1] * inv0);
            store_h16(g_y, y1 + d, o[nt][2] * inv1, o[nt][3] * inv1);
        }

        __syncthreads();   // all warps done with smem before next phase
    }
}

// ---------------------------------------------------------------------------
// Launch: x, cos, sin, Wq, Wk, Wv, Wo. out = f32 [B,T,C].
// ---------------------------------------------------------------------------
extern "C" void kernel_launch(void* const* d_in, const int* in_sizes, int n_in,
                              void* d_out, int out_size)
{
    const float* x    = (const float*)d_in[0];
    const float* cosb = (const float*)d_in[1];
    const float* sinb = (const float*)d_in[2];
    const float* Wq   = (const float*)d_in[3];
    const float* Wk   = (const float*)d_in[4];
    const float* Wv   = (const float*)d_in[5];
    const float* Wo   = (const float*)d_in[6];
    float* out = (float*)d_out;

    static bool attr_set = false;
    if (!attr_set) {
        cudaFuncSetAttribute(attn_kernel,
                             cudaFuncAttributeMaxDynamicSharedMemorySize, 49152);
        cudaFuncSetAttribute(gemm_fp16<0>,
                             cudaFuncAttributeMaxDynamicSharedMemorySize, 88064);
        cudaFuncSetAttribute(gemm_fp16<1>,
                             cudaFuncAttributeMaxDynamicSharedMemorySize, 107520);
        attr_set = true;
    }

    // 0. one merged fp32 -> fp16 conversion (weights permuted for rope pairs)
    cvt_all<<<6656, 256>>>(x, Wq, Wk, Wv, Wo);

    // 1. fused QKV projection + RoPE + scale (fp16, 128x192, BK=64, 2-stage)
    gemm_fp16<0><<<dim3(8, 32), 256, 88064>>>(cosb, sinb, nullptr);

    // 2. causal flash attention (fp16, paired q-tiles, single balanced wave)
    attn_kernel<<<dim3(16, 32), 128, 49152>>>();

    // 3. output projection (fp16, 128x128, BK=64, 3-stage)
    gemm_fp16<1><<<dim3(8, 32), 256, 107520>>>(nullptr, nullptr, out);
}

// round 17
// speedup vs baseline: 1.0777x; 1.0137x over previous
#include <cuda_runtime.h>
#include <cuda_bf16.h>
#include <cuda_fp16.h>
#include <cstdint>

// ---------------------------------------------------------------------------
// GQA: B=2, T=2048, C=1024, H=16 q-heads, KVH=4 kv-heads, D=64, causal, RoPE
// Full single-fp16 pipeline (fp32 accum). Q/K head-dims stored PERMUTED in
// interleaved rope-pair order (QK^T invariant; RoPE = register math).
// gemm0: BK=64 2-stage; gemm1: BK=32 3-stage. Attention: 64-key tiles,
// 3-stage ring, 4 CTAs/SM, triangular-paired CTAs, conditional rescale,
// softmax exp via ex2.approx.f16x2 (output doubles as PV A-fragment).
// ---------------------------------------------------------------------------

__device__ __align__(16) __half g_x[4194304];
__device__ __align__(16) __half g_wqkv[1572864];   // [K=1024][N=1536], Q/K cols permuted
__device__ __align__(16) __half g_wo[1048576];
__device__ __align__(16) __half g_q[4194304];      // permuted head-dim
__device__ __align__(16) __half g_k[1048576];      // permuted head-dim
__device__ __align__(16) __half g_v[1048576];
__device__ __align__(16) __half g_y[4194304];

// ---------------------------------------------------------------------------
// helpers
// ---------------------------------------------------------------------------
__device__ __forceinline__ uint32_t smem_u32(const void* p) {
    return (uint32_t)__cvta_generic_to_shared(p);
}
__device__ __forceinline__ void ldmx4(uint32_t* r, uint32_t addr) {
    asm volatile("ldmatrix.sync.aligned.m8n8.x4.shared.b16 {%0,%1,%2,%3}, [%4];"
        : "=r"(r[0]), "=r"(r[1]), "=r"(r[2]), "=r"(r[3]) : "r"(addr));
}
__device__ __forceinline__ void ldmx4t(uint32_t* r, uint32_t addr) {
    asm volatile("ldmatrix.sync.aligned.m8n8.x4.trans.shared.b16 {%0,%1,%2,%3}, [%4];"
        : "=r"(r[0]), "=r"(r[1]), "=r"(r[2]), "=r"(r[3]) : "r"(addr));
}
__device__ __forceinline__ void mma_f16(float* c, const uint32_t* a, const uint32_t* b) {
    asm volatile(
        "mma.sync.aligned.m16n8k16.row.col.f32.f16.f16.f32 "
        "{%0,%1,%2,%3}, {%4,%5,%6,%7}, {%8,%9}, {%0,%1,%2,%3};\n"
        : "+f"(c[0]), "+f"(c[1]), "+f"(c[2]), "+f"(c[3])
        : "r"(a[0]), "r"(a[1]), "r"(a[2]), "r"(a[3]), "r"(b[0]), "r"(b[1]));
}
__device__ __forceinline__ float ex2(float x) {
    float r;
    asm("ex2.approx.f32 %0, %1;" : "=f"(r) : "f"(x));
    return r;
}
// packed fp16 exp2 of two fp32 deltas; result usable directly as MMA A-frag
__device__ __forceinline__ uint32_t ex2h2(float a, float b) {
    __half2 h = __floats2half2_rn(a, b);
    uint32_t r;
    asm("ex2.approx.f16x2 %0, %1;" : "=r"(r) : "r"(*(uint32_t*)&h));
    return r;
}
__device__ __forceinline__ void store_h16(__half* H, int idx, float a, float b) {
    __half2 hv = __floats2half2_rn(a, b);
    *(__half2*)(H + idx) = hv;
}
__device__ __forceinline__ uint2 cvt4_f16(float4 v) {
    __half2 h0 = __floats2half2_rn(v.x, v.y);
    __half2 h1 = __floats2half2_rn(v.z, v.w);
    uint2 r; r.x = *(uint32_t*)&h0; r.y = *(uint32_t*)&h1;
    return r;
}
__device__ __forceinline__ void cpa16(uint32_t dst, const void* src) {
    asm volatile("cp.async.cg.shared.global [%0], [%1], 16;\n" :: "r"(dst), "l"(src));
}

#define SOFTMAX_SCALE (0.125f * 1.44269504088896f)  // 1/sqrt(64) * log2(e)

// ---------------------------------------------------------------------------
// Single merged conversion kernel (fp32 -> fp16, weights permuted for rope).
// ---------------------------------------------------------------------------
__global__ void cvt_all(const float* __restrict__ x,
                        const float* __restrict__ Wq,
                        const float* __restrict__ Wk,
                        const float* __restrict__ Wv,
                        const float* __restrict__ Wo)
{
    int blk = blockIdx.x;
    if (blk < 4096) {
        int i = blk * 256 + threadIdx.x;
        ((uint2*)g_x)[i] = cvt4_f16(((const float4*)x)[i]);
    } else if (blk < 5632) {
        int i = (blk - 4096) * 256 + threadIdx.x;
        int k  = i / 384;
        int n4 = (i % 384) * 4;
        float4 v;
        if (n4 < 1024) {
            int h = n4 >> 6, ch = n4 & 63, j = ch >> 1;
            const float* wr = Wq + k * 1024 + h * 64;
            v.x = wr[j];      v.y = wr[j + 32];
            v.z = wr[j + 1];  v.w = wr[j + 33];
        } else if (n4 < 1280) {
            int m = n4 - 1024;
            int h = m >> 6, ch = m & 63, j = ch >> 1;
            const float* wr = Wk + k * 256 + h * 64;
            v.x = wr[j];      v.y = wr[j + 32];
            v.z = wr[j + 1];  v.w = wr[j + 33];
        } else {
            v = *(const float4*)(Wv + k * 256 + n4 - 1280);
        }
        *(uint2*)(g_wqkv + k * 1536 + n4) = cvt4_f16(v);
    } else {
        int i = (blk - 5632) * 256 + threadIdx.x;
        ((uint2*)g_wo)[i] = cvt4_f16(((const float4*)Wo)[i]);
    }
}

// ---------------------------------------------------------------------------
// fp16 GEMM (fp32 accum), 2 CTAs/SM.
// MODE 0: tile 128x192, BK=64, 2-stage; grid 8x32 (one wave); rope epilogue.
// MODE 1: tile 128x128, BK=32, 3-stage; grid 8x32; fp32 epilogue -> Cout.
// ---------------------------------------------------------------------------
template<int MODE>
__global__ void __launch_bounds__(256, 2) gemm_fp16(
    const float* __restrict__ cosb,
    const float* __restrict__ sinb,
    float* __restrict__ Cout)
{
    constexpr int NT     = (MODE == 0) ? 192 : 128;
    constexpr int BK     = (MODE == 0) ? 64 : 32;
    constexpr int NSTAGE = (MODE == 0) ? 2 : 3;
    constexpr int NWARP  = NT / 2;
    constexpr int NF     = NWARP / 8;
    constexpr int APITCH = BK + 8;
    constexpr int BPITCH = NT + 8;
    constexpr int ABYTES = 128 * APITCH * 2;
    constexpr int STAGE  = ABYTES + BK * BPITCH * 2;
    constexpr int ACH    = 16 * BK;                  // A 16B chunks
    constexpr int BCH    = BK * (NT / 8);            // B 16B chunks
    constexpr int ITERS  = (ACH + BCH) / 256;
    constexpr int NKI    = 1024 / BK;
    constexpr int KS     = BK / 16;
    const int ldn = (MODE == 0) ? 1536 : 1024;

    extern __shared__ __align__(16) __half sm[];
    const uint32_t sbase = smem_u32(sm);

    const __half* A = (MODE == 0) ? g_x : g_y;
    const __half* B = (MODE == 0) ? g_wqkv : g_wo;

    const int tid  = threadIdx.x;
    const int lane = tid & 31;
    const int warp = tid >> 5;
    const int wm   = warp >> 1;
    const int wn   = warp & 1;
    const int brow = blockIdx.y * 128;
    const int bcol = blockIdx.x * NT;
    const int t4   = lane & 3;

    float c[2][NF][4];
    #pragma unroll
    for (int mt = 0; mt < 2; mt++)
        #pragma unroll
        for (int nt = 0; nt < NF; nt++)
            #pragma unroll
            for (int i = 0; i < 4; i++) c[mt][nt][i] = 0.f;

    auto stage = [&](int ki, int buf) {
        int kb = ki * BK;
        uint32_t base = sbase + (uint32_t)(buf * STAGE);
        #pragma unroll
        for (int i = 0; i < ITERS; i++) {
            int u = tid + i * 256;
            if (u < ACH) {
                int ar = u / (BK / 8), ac8 = (u % (BK / 8)) * 8;
                cpa16(base + (uint32_t)(ar * APITCH + ac8) * 2u,
                      A + (brow + ar) * 1024 + kb + ac8);
            } else {
                int v = u - ACH;
                int br2 = v / (NT / 8), bc8 = (v % (NT / 8)) * 8;
                cpa16(base + (uint32_t)ABYTES + (uint32_t)(br2 * BPITCH + bc8) * 2u,
                      B + (kb + br2) * ldn + bcol + bc8);
            }
        }
        asm volatile("cp.async.commit_group;\n" ::: "memory");
    };

    stage(0, 0);
    if (NSTAGE == 3) stage(1, 1);

    for (int ki = 0; ki < NKI; ki++) {
        int buf = ki % NSTAGE;
        if (NSTAGE == 3) {
            if (ki == NKI - 1) asm volatile("cp.async.wait_group 0;\n" ::: "memory");
            else               asm volatile("cp.async.wait_group 1;\n" ::: "memory");
        } else {
            asm volatile("cp.async.wait_group 0;\n" ::: "memory");
        }
        __syncthreads();

        if (NSTAGE == 3) {
            if (ki + 2 < NKI) stage(ki + 2, (ki + 2) % 3);
        } else {
            if (ki + 1 < NKI) stage(ki + 1, (ki + 1) & 1);
        }

        uint32_t bA = sbase + (uint32_t)(buf * STAGE);
        uint32_t bB = bA + (uint32_t)ABYTES;

        #pragma unroll
        for (int ks = 0; ks < KS; ks++) {
            uint32_t a[2][4];
            #pragma unroll
            for (int mt = 0; mt < 2; mt++) {
                uint32_t off = 2u * ((uint32_t)(wm * 32 + mt * 16 + (lane & 15)) * APITCH
                                     + ks * 16 + ((lane >> 4) << 3));
                ldmx4(a[mt], bA + off);
            }
            #pragma unroll
            for (int npp = 0; npp < NF / 2; npp++) {
                uint32_t b4[4];
                uint32_t off = 2u * ((uint32_t)(ks * 16 + (lane & 15)) * BPITCH
                                     + wn * NWARP + npp * 16 + ((lane >> 4) << 3));
                ldmx4t(b4, bB + off);
                #pragma unroll
                for (int sub = 0; sub < 2; sub++) {
                    mma_f16(c[0][npp * 2 + sub], a[0], &b4[sub * 2]);
                    mma_f16(c[1][npp * 2 + sub], a[1], &b4[sub * 2]);
                }
            }
        }
    }

    if (MODE == 1) {
        #pragma unroll
        for (int mt = 0; mt < 2; mt++) {
            int r0 = brow + wm * 32 + mt * 16 + (lane >> 2);
            #pragma unroll
            for (int nt = 0; nt < NF; nt++) {
                int cc = bcol + wn * NWARP + nt * 8 + (t4 << 1);
                float2 v0; v0.x = c[mt][nt][0]; v0.y = c[mt][nt][1];
                float2 v1; v1.x = c[mt][nt][2]; v1.y = c[mt][nt][3];
                *(float2*)(Cout + r0 * 1024 + cc)       = v0;
                *(float2*)(Cout + (r0 + 8) * 1024 + cc) = v1;
            }
        }
    } else {
        #pragma unroll
        for (int mt = 0; mt < 2; mt++) {
            int r0 = brow + wm * 32 + mt * 16 + (lane >> 2);
            int r1 = r0 + 8;
            int b0 = r0 >> 11, t0 = r0 & 2047;
            int b1 = r1 >> 11, t1 = r1 & 2047;
            #pragma unroll
            for (int nt = 0; nt < NF; nt++) {
                int cc = bcol + wn * NWARP + nt * 8 + (t4 << 1);
                if (cc < 1280) {
                    bool isq = (cc < 1024);
                    int m  = isq ? cc : cc - 1024;
                    int h  = m >> 6, ch = m & 63, j = ch >> 1;
                    int nh = isq ? 16 : 4;
                    float sc = isq ? SOFTMAX_SCALE : 1.f;
                    __half* H = isq ? g_q : g_k;
                    float cs0 = cosb[t0 * 32 + j], sn0 = sinb[t0 * 32 + j];
                    float cs1 = cosb[t1 * 32 + j], sn1 = sinb[t1 * 32 + j];
                    float x1 = c[mt][nt][0], x2 = c[mt][nt][1];
                    store_h16(H, ((b0 * nh + h) * 2048 + t0) * 64 + ch,
                              (x1 * cs0 - x2 * sn0) * sc, (x2 * cs0 + x1 * sn0) * sc);
                    x1 = c[mt][nt][2]; x2 = c[mt][nt][3];
                    store_h16(H, ((b1 * nh + h) * 2048 + t1) * 64 + ch,
                              (x1 * cs1 - x2 * sn1) * sc, (x2 * cs1 + x1 * sn1) * sc);
                } else {
                    int m = cc - 1280;
                    int h = m >> 6, d = m & 63;
                    store_h16(g_v, ((b0 * 4 + h) * 2048 + t0) * 64 + d,
                              c[mt][nt][0], c[mt][nt][1]);
                    store_h16(g_v, ((b1 * 4 + h) * 2048 + t1) * 64 + d,
                              c[mt][nt][2], c[mt][nt][3]);
                }
            }
        }
    }
}

// ---------------------------------------------------------------------------
// MMA flash attention, fp16 x1, 64-key tiles, 3-stage ring, ONE sync per
// tile, 4 CTAs/SM, triangular-paired CTAs (grid 16x32, q-tiles bx & 31-bx).
// Softmax exp via ex2.approx.f16x2 -> result IS the PV A-fragment.
// ---------------------------------------------------------------------------
__global__ void __launch_bounds__(128, 4) attn_kernel()
{
    extern __shared__ __align__(16) __half smem[];
    const uint32_t sbase = smem_u32(smem);

    const int tid  = threadIdx.x;
    const int lane = tid & 31;
    const int warp = tid >> 5;
    const int g    = lane >> 2;
    const int t4   = lane & 3;
    const int bh   = blockIdx.y;
    const int b    = bh >> 4, hh = bh & 15;
    const int kh   = hh >> 2;

    const __half* srcK = g_k + ((b * 4 + kh) * 2048) * 64;
    const __half* srcV = g_v + ((b * 4 + kh) * 2048) * 64;

    auto stage = [&](int kt, int buf) {
        uint32_t base = sbase + (uint32_t)buf * 16384u;
        #pragma unroll
        for (int i = 0; i < 4; i++) {
            int u = tid + i * 128;
            int row = u >> 3, ch = u & 7;
            uint32_t sw = (uint32_t)(row * 128) + (uint32_t)((ch ^ (row & 7)) << 4);
            cpa16(base +          sw, srcK + kt * 4096 + u * 8);
            cpa16(base + 8192u  + sw, srcV + kt * 4096 + u * 8);
        }
        asm volatile("cp.async.commit_group;\n" ::: "memory");
    };

    #pragma unroll 1
    for (int ph = 0; ph < 2; ph++) {
        const int qt = ph ? (31 - (int)blockIdx.x) : (int)blockIdx.x;

        const int r0 = qt * 64 + warp * 16 + g;
        const int r1 = r0 + 8;
        const int warp_min_row = qt * 64 + warp * 16;

        uint32_t qf[4][4];
        {
            const __half* q0 = g_q + (bh * 2048 + r0) * 64;
            const __half* q1 = g_q + (bh * 2048 + r1) * 64;
            #pragma unroll
            for (int ks = 0; ks < 4; ks++) {
                int cb = ks * 16 + (t4 << 1);
                qf[ks][0] = *(const uint32_t*)(q0 + cb);
                qf[ks][1] = *(const uint32_t*)(q1 + cb);
                qf[ks][2] = *(const uint32_t*)(q0 + cb + 8);
                qf[ks][3] = *(const uint32_t*)(q1 + cb + 8);
            }
        }

        float o[8][4];
        #pragma unroll
        for (int nt = 0; nt < 8; nt++)
            #pragma unroll
            for (int i = 0; i < 4; i++) o[nt][i] = 0.f;
        float m0 = -1e30f, m1 = -1e30f, l0 = 0.f, l1 = 0.f;

        const int ntiles = qt + 1;

        stage(0, 0);
        if (ntiles > 1) stage(1, 1);

        for (int kt = 0; kt < ntiles; kt++) {
            int buf = kt % 3;
            if (kt == ntiles - 1) {
                asm volatile("cp.async.wait_group 0;\n" ::: "memory");
            } else {
                asm volatile("cp.async.wait_group 1;\n" ::: "memory");
            }
            __syncthreads();

            {
                const uint32_t bK = sbase + (uint32_t)buf * 16384u;
                const uint32_t bV = bK + 8192u;

                float s[8][4];
                #pragma unroll
                for (int nt = 0; nt < 8; nt++)
                    #pragma unroll
                    for (int i = 0; i < 4; i++) s[nt][i] = 0.f;

                #pragma unroll
                for (int ks = 0; ks < 4; ks++) {
                    uint32_t kb[4][4];
                    #pragma unroll
                    for (int pr = 0; pr < 4; pr++) {
                        int n_idx = pr * 16 + (lane & 7) + ((lane >> 4) << 3);
                        int chv   = 2 * ks + ((lane >> 3) & 1);
                        uint32_t off = (uint32_t)(n_idx * 128)
                                     + (uint32_t)((chv ^ (n_idx & 7)) << 4);
                        ldmx4(kb[pr], bK + off);
                    }
                    #pragma unroll
                    for (int pr = 0; pr < 4; pr++)
                        #pragma unroll
                        for (int sub = 0; sub < 2; sub++)
                            mma_f16(s[pr * 2 + sub], qf[ks], &kb[pr][sub * 2]);
                }

                if (kt * 64 + 63 > warp_min_row) {
                    #pragma unroll
                    for (int nt = 0; nt < 8; nt++) {
                        int c0 = kt * 64 + nt * 8 + (t4 << 1);
                        if (c0     > r0) s[nt][0] = -1e30f;
                        if (c0 + 1 > r0) s[nt][1] = -1e30f;
                        if (c0     > r1) s[nt][2] = -1e30f;
                        if (c0 + 1 > r1) s[nt][3] = -1e30f;
                    }
                }

                float t0 = -1e30f, t1 = -1e30f;
                #pragma unroll
                for (int nt = 0; nt < 8; nt++) {
                    t0 = fmaxf(t0, fmaxf(s[nt][0], s[nt][1]));
                    t1 = fmaxf(t1, fmaxf(s[nt][2], s[nt][3]));
                }
                t0 = fmaxf(t0, __shfl_xor_sync(0xffffffffu, t0, 1));
                t0 = fmaxf(t0, __shfl_xor_sync(0xffffffffu, t0, 2));
                t1 = fmaxf(t1, __shfl_xor_sync(0xffffffffu, t1, 1));
                t1 = fmaxf(t1, __shfl_xor_sync(0xffffffffu, t1, 2));

                if (t0 > m0 || t1 > m1) {        // rescale only when max moves
                    float m0n = fmaxf(m0, t0), m1n = fmaxf(m1, t1);
                    float c0f = ex2(m0 - m0n), c1f = ex2(m1 - m1n);
                    m0 = m0n; m1 = m1n;
                    l0 *= c0f; l1 *= c1f;
                    #pragma unroll
                    for (int nt = 0; nt < 8; nt++) {
                        o[nt][0] *= c0f; o[nt][1] *= c0f;
                        o[nt][2] *= c1f; o[nt][3] *= c1f;
                    }
                }

                // ---- p = exp2(s - m) in packed fp16; feed MMA directly ----
                float sum0 = 0.f, sum1 = 0.f;
                #pragma unroll
                for (int ks = 0; ks < 4; ks++) {
                    uint32_t aP[4];
                    aP[0] = ex2h2(s[2*ks][0]   - m0, s[2*ks][1]   - m0);
                    aP[1] = ex2h2(s[2*ks][2]   - m1, s[2*ks][3]   - m1);
                    aP[2] = ex2h2(s[2*ks+1][0] - m0, s[2*ks+1][1] - m0);
                    aP[3] = ex2h2(s[2*ks+1][2] - m1, s[2*ks+1][3] - m1);

                    float2 f;
                    f = __half22float2(*(__half2*)&aP[0]); sum0 += f.x + f.y;
                    f = __half22float2(*(__half2*)&aP[1]); sum1 += f.x + f.y;
                    f = __half22float2(*(__half2*)&aP[2]); sum0 += f.x + f.y;
                    f = __half22float2(*(__half2*)&aP[3]); sum1 += f.x + f.y;

                    #pragma unroll
                    for (int dp = 0; dp < 4; dp++) {
                        uint32_t vf[4];
                        int row  = 16 * ks + (lane & 15);
                        int chv  = dp * 2 + (lane >> 4);
                        uint32_t off = (uint32_t)(row * 128)
                                     + (uint32_t)((chv ^ (row & 7)) << 4);
                        ldmx4t(vf, bV + off);
                        mma_f16(o[dp * 2 + 0], aP, &vf[0]);
                        mma_f16(o[dp * 2 + 1], aP, &vf[2]);
                    }
                }
                l0 += sum0;
                l1 += sum1;
            }

            if (kt + 2 < ntiles) stage(kt + 2, (kt + 2) % 3);
        }

        l0 += __shfl_xor_sync(0xffffffffu, l0, 1);
        l0 += __shfl_xor_sync(0xffffffffu, l0, 2);
        l1 += __shfl_xor_sync(0xffffffffu, l1, 1);
        l1 += __shfl_xor_sync(0xffffffffu, l1, 2);
        float inv0 = 1.f / l0, inv1 = 1.f / l1;

        int y0 = (b * 2048 + r0) * 1024 + hh * 64;
        int y1 = (b * 2048 + r1) * 1024 + hh * 64;
        #pragma unroll
        for (int nt = 0; nt < 8; nt++) {
            int d = nt * 8 + (t4 << 1);
            store_h16(g_y, y0 + d, o[nt][0] * inv0, o[nt][1] * inv0);
            store_h16(g_y, y1 + d, o[nt][2] * inv1, o[nt][3] * inv1);
        }

        __syncthreads();   // all warps done with smem before next phase
    }
}

// ---------------------------------------------------------------------------
// Launch: x, cos, sin, Wq, Wk, Wv, Wo. out = f32 [B,T,C].
// ---------------------------------------------------------------------------
extern "C" void kernel_launch(void* const* d_in, const int* in_sizes, int n_in,
                              void* d_out, int out_size)
{
    const float* x    = (const float*)d_in[0];
    const float* cosb = (const float*)d_in[1];
    const float* sinb = (const float*)d_in[2];
    const float* Wq   = (const float*)d_in[3];
    const float* Wk   = (const float*)d_in[4];
    const float* Wv   = (const float*)d_in[5];
    const float* Wo   = (const float*)d_in[6];
    float* out = (float*)d_out;

    static bool attr_set = false;
    if (!attr_set) {
        cudaFuncSetAttribute(attn_kernel,
                             cudaFuncAttributeMaxDynamicSharedMemorySize, 49152);
        cudaFuncSetAttribute(gemm_fp16<0>,
                             cudaFuncAttributeMaxDynamicSharedMemorySize, 88064);
        cudaFuncSetAttribute(gemm_fp16<1>,
                             cudaFuncAttributeMaxDynamicSharedMemorySize, 56832);
        attr_set = true;
    }

    // 0. one merged fp32 -> fp16 conversion (weights permuted for rope pairs)
    cvt_all<<<6656, 256>>>(x, Wq, Wk, Wv, Wo);

    // 1. fused QKV projection + RoPE + scale (fp16, 128x192, BK=64, 2-stage)
    gemm_fp16<0><<<dim3(8, 32), 256, 88064>>>(cosb, sinb, nullptr);

    // 2. causal flash attention (fp16, paired q-tiles, f16x2 exp softmax)
    attn_kernel<<<dim3(16, 32), 128, 49152>>>();

    // 3. output projection (fp16, 128x128, BK=32, 3-stage)
    gemm_fp16<1><<<dim3(8, 32), 256, 56832>>>(nullptr, nullptr, out);
}